// round 10
// baseline (speedup 1.0000x reference)
#include <cuda_runtime.h>
#include <math.h>
#include <stdint.h>

// Problem constants
#define Bb 2
#define Ss 2048
#define Ee 1024
#define Hh 16
#define Dd 64
#define Mtot (Bb*Ss)   // 4096
#define Kdim Ee        // 1024
#define Ndim Ee        // 1024

// -------- device scratch (no allocations allowed) --------
__device__ float g_WT[4][Ee*Ee];          // transposed weights
__device__ float g_q[Bb*Hh*Ss*Dd];        // (b,h,s,d)
__device__ float g_k[Bb*Hh*Ss*Dd];
__device__ float g_v[Bb*Hh*Ss*Dd];
__device__ float g_ao[Mtot*Ee];           // attention output (b,s,h*D+d)

// ============================================================
// Transpose all 4 weight matrices: WT[k][n] = W[n][k]
// ============================================================
__global__ void transpose4_kernel(const float* __restrict__ w0, const float* __restrict__ w1,
                                  const float* __restrict__ w2, const float* __restrict__ w3)
{
    __shared__ float t[32][33];
    const float* W = (blockIdx.z == 0) ? w0 : (blockIdx.z == 1) ? w1 : (blockIdx.z == 2) ? w2 : w3;
    float* WT = g_WT[blockIdx.z];

    int x = blockIdx.x * 32 + threadIdx.x;   // k
    int y = blockIdx.y * 32 + threadIdx.y;   // n
    #pragma unroll
    for (int i = 0; i < 32; i += 8)
        t[threadIdx.y + i][threadIdx.x] = W[(size_t)(y + i) * Kdim + x];
    __syncthreads();
    x = blockIdx.y * 32 + threadIdx.x;       // n
    y = blockIdx.x * 32 + threadIdx.y;       // k
    #pragma unroll
    for (int i = 0; i < 32; i += 8)
        WT[(size_t)(y + i) * Ndim + x] = t[threadIdx.x][threadIdx.y + i];
}

// ============================================================
// 3xTF32 tensor-core GEMM.  blockIdx.x = mat*8 + n_tile; per-mat
// A/B/bias/C selection (QKV fused in one launch; O uses mat 0).
// mode 0: row-major C.  mode 1: head-split write (b,h,s,d).
// 128x128 block, BK=16, 256 thr = 8 warps (2x4), warp tile 64x32.
// Audited: fragment maps match PTX m16n8k8 row.col tf32 layouts;
// A-frag (stride 20) and B-frag (stride 136) LDS are conflict-free.
// ============================================================
#define BM 128
#define BN 128
#define BK 16
#define ASTR 20
#define BSTR 136
#define ABUF (BM*ASTR)
#define BBUF (BK*BSTR)
#define BUFSZ (2*ABUF + 2*BBUF)
#define GSMEM (2*BUFSZ*4)        // 75776 bytes

__device__ __forceinline__ unsigned f2tf32(float x) {
    unsigned u; asm("cvt.rna.tf32.f32 %0, %1;" : "=r"(u) : "f"(x)); return u;
}

__device__ __forceinline__ void split_store4(float* hi, float* lo, float4 v) {
    float hx = __uint_as_float(f2tf32(v.x));
    float hy = __uint_as_float(f2tf32(v.y));
    float hz = __uint_as_float(f2tf32(v.z));
    float hw = __uint_as_float(f2tf32(v.w));
    *(float4*)hi = make_float4(hx, hy, hz, hw);
    *(float4*)lo = make_float4(__uint_as_float(f2tf32(v.x - hx)),
                               __uint_as_float(f2tf32(v.y - hy)),
                               __uint_as_float(f2tf32(v.z - hz)),
                               __uint_as_float(f2tf32(v.w - hw)));
}

__device__ __forceinline__ void mma_tf32(float* c, const unsigned* a, const unsigned* b) {
    asm volatile("mma.sync.aligned.m16n8k8.row.col.f32.tf32.tf32.f32 "
        "{%0,%1,%2,%3}, {%4,%5,%6,%7}, {%8,%9}, {%0,%1,%2,%3};"
        : "+f"(c[0]), "+f"(c[1]), "+f"(c[2]), "+f"(c[3])
        : "r"(a[0]), "r"(a[1]), "r"(a[2]), "r"(a[3]), "r"(b[0]), "r"(b[1]));
}

__global__ __launch_bounds__(256) void gemm_tf32_kernel(
    const float* __restrict__ A0, const float* __restrict__ A1,
    const float* __restrict__ A2, const float* __restrict__ WTbase,
    const float* __restrict__ bias0, const float* __restrict__ bias1,
    const float* __restrict__ bias2,
    float* __restrict__ C0, float* __restrict__ C1, float* __restrict__ C2,
    int mode)
{
    extern __shared__ float smw[];
    int tid = threadIdx.x;
    int wid = tid >> 5, lane = tid & 31;
    int g = lane >> 2, kq = lane & 3;

    int mat = blockIdx.x >> 3;
    const float* A    = (mat == 0) ? A0 : (mat == 1) ? A1 : A2;
    const float* Bmat = WTbase + (size_t)mat * Ee * Ee;
    const float* bias = (mat == 0) ? bias0 : (mat == 1) ? bias1 : bias2;
    float* C          = (mat == 0) ? C0 : (mat == 1) ? C1 : C2;

    int m0 = blockIdx.y * BM, n0 = (blockIdx.x & 7) * BN;
    int wm = (wid >> 2) * 64, wn = (wid & 3) * 32;

    int ar = tid >> 1;              // 0..127 (A row)
    int ak = (tid & 1) * 8;         // 0 or 8
    int br = tid >> 4;              // 0..15  (B row = k)
    int bn = (tid & 15) * 4;        // +0, +64

    const float* Ag = A + (size_t)(m0 + ar) * Kdim + ak;
    const float* Bg = Bmat + (size_t)br * Ndim + n0 + bn;

    float c[4][4][4];
    #pragma unroll
    for (int i = 0; i < 4; i++)
        #pragma unroll
        for (int j = 0; j < 4; j++)
            #pragma unroll
            for (int t = 0; t < 4; t++) c[i][j][t] = 0.f;

    float4 va0, va1, vb0, vb1;

    va0 = *(const float4*)Ag;
    va1 = *(const float4*)(Ag + 4);
    vb0 = *(const float4*)Bg;
    vb1 = *(const float4*)(Bg + 64);
    {
        float* Ah = smw;              float* Al = Ah + ABUF;
        float* Bh = smw + 2 * ABUF;   float* Bl = Bh + BBUF;
        split_store4(&Ah[ar*ASTR + ak],     &Al[ar*ASTR + ak],     va0);
        split_store4(&Ah[ar*ASTR + ak + 4], &Al[ar*ASTR + ak + 4], va1);
        split_store4(&Bh[br*BSTR + bn],      &Bl[br*BSTR + bn],      vb0);
        split_store4(&Bh[br*BSTR + bn + 64], &Bl[br*BSTR + bn + 64], vb1);
    }
    __syncthreads();

    int buf = 0;
    for (int k0 = 0; k0 < Kdim; k0 += BK) {
        bool nxt = (k0 + BK) < Kdim;
        if (nxt) {
            va0 = *(const float4*)(Ag + k0 + BK);
            va1 = *(const float4*)(Ag + k0 + BK + 4);
            vb0 = *(const float4*)(Bg + (size_t)(k0 + BK) * Ndim);
            vb1 = *(const float4*)(Bg + (size_t)(k0 + BK) * Ndim + 64);
        }

        const float* Ah = smw + buf * BUFSZ;
        const float* Al = Ah + ABUF;
        const float* Bh = Ah + 2 * ABUF;
        const float* Bl = Bh + BBUF;

        #pragma unroll
        for (int ks = 0; ks < 2; ks++) {
            int k8 = ks * 8;
            unsigned bhf[4][2], blf[4][2];
            #pragma unroll
            for (int tn = 0; tn < 4; tn++) {
                int colb = wn + 8 * tn + g;
                bhf[tn][0] = __float_as_uint(Bh[(k8 + kq) * BSTR + colb]);
                bhf[tn][1] = __float_as_uint(Bh[(k8 + kq + 4) * BSTR + colb]);
                blf[tn][0] = __float_as_uint(Bl[(k8 + kq) * BSTR + colb]);
                blf[tn][1] = __float_as_uint(Bl[(k8 + kq + 4) * BSTR + colb]);
            }
            #pragma unroll
            for (int tm = 0; tm < 4; tm++) {
                int r0 = wm + 16 * tm + g;
                unsigned ahf[4], alf[4];
                ahf[0] = __float_as_uint(Ah[(r0    ) * ASTR + k8 + kq]);
                ahf[1] = __float_as_uint(Ah[(r0 + 8) * ASTR + k8 + kq]);
                ahf[2] = __float_as_uint(Ah[(r0    ) * ASTR + k8 + kq + 4]);
                ahf[3] = __float_as_uint(Ah[(r0 + 8) * ASTR + k8 + kq + 4]);
                alf[0] = __float_as_uint(Al[(r0    ) * ASTR + k8 + kq]);
                alf[1] = __float_as_uint(Al[(r0 + 8) * ASTR + k8 + kq]);
                alf[2] = __float_as_uint(Al[(r0    ) * ASTR + k8 + kq + 4]);
                alf[3] = __float_as_uint(Al[(r0 + 8) * ASTR + k8 + kq + 4]);
                #pragma unroll
                for (int tn = 0; tn < 4; tn++) {
                    mma_tf32(c[tm][tn], ahf, bhf[tn]);   // hi*hi
                    mma_tf32(c[tm][tn], alf, bhf[tn]);   // lo*hi
                    mma_tf32(c[tm][tn], ahf, blf[tn]);   // hi*lo
                }
            }
        }

        if (nxt) {
            int nb = buf ^ 1;
            float* nAh = smw + nb * BUFSZ;  float* nAl = nAh + ABUF;
            float* nBh = nAh + 2 * ABUF;    float* nBl = nBh + BBUF;
            split_store4(&nAh[ar*ASTR + ak],     &nAl[ar*ASTR + ak],     va0);
            split_store4(&nAh[ar*ASTR + ak + 4], &nAl[ar*ASTR + ak + 4], va1);
            split_store4(&nBh[br*BSTR + bn],      &nBl[br*BSTR + bn],      vb0);
            split_store4(&nBh[br*BSTR + bn + 64], &nBl[br*BSTR + bn + 64], vb1);
            __syncthreads();
            buf = nb;
        }
    }

    #pragma unroll
    for (int tn = 0; tn < 4; tn++) {
        int col = n0 + wn + 8 * tn + 2 * kq;
        float b0 = bias[col], b1 = bias[col + 1];
        #pragma unroll
        for (int tm = 0; tm < 4; tm++) {
            int ma = m0 + wm + 16 * tm + g;
            int mb = ma + 8;
            float2 ra = make_float2(c[tm][tn][0] + b0, c[tm][tn][1] + b1);
            float2 rb = make_float2(c[tm][tn][2] + b0, c[tm][tn][3] + b1);
            if (mode == 0) {
                *(float2*)&C[(size_t)ma * Ndim + col] = ra;
                *(float2*)&C[(size_t)mb * Ndim + col] = rb;
            } else {
                int h = col >> 6, d = col & 63;
                int ba_ = ma >> 11, sa = ma & 2047;
                int bb_ = mb >> 11, sb = mb & 2047;
                *(float2*)&C[((size_t)(ba_ * Hh + h) * Ss + sa) * Dd + d] = ra;
                *(float2*)&C[((size_t)(bb_ * Hh + h) * Ss + sb) * Dd + d] = rb;
            }
        }
    }
}

// ============================================================
// Fast exp2 on the FMA pipe (MUFU rt=8/SMSP would bottleneck softmax).
// Domain after clamp: [-126, 0]; max rel err ~4e-5.
// ============================================================
__device__ __forceinline__ float fast_exp2(float x) {
    x = fmaxf(x, -126.f);
    float r = rintf(x);
    float f = x - r;                  // [-0.5, 0.5]
    float p = 0.00961812910f;
    p = fmaf(p, f, 0.05550410866f);
    p = fmaf(p, f, 0.24022650696f);
    p = fmaf(p, f, 0.69314718056f);
    p = fmaf(p, f, 1.0f);
    int e = (int)r;
    return p * __int_as_float((e + 127) << 23);
}

// ============================================================
// Flash attention, causal, base-2 softmax. 64x64 tiles, 256 threads.
// Thread microtile: rows rg+16i (i<4) x score cols cg+16j (j<4);
// output dims cg*4..cg*4+3.
// Audited: Q/P-scalar LDS are per-phase broadcast; K/V float4 2-way
// (floor for 16 rows over 8 bank-quads); -INF/mask/exp2 edge cases safe.
// ============================================================
#define APAD 68
#define ASMEM (3 * 64 * APAD * 4)
#define QSCALE (0.125f * 1.44269504088896340736f)

__global__ __launch_bounds__(256) void attn_kernel(
    const float* __restrict__ gq, const float* __restrict__ gk,
    const float* __restrict__ gv, float* __restrict__ gao)
{
    extern __shared__ float sm[];
    float* Qs  = sm;
    float* KPs = sm + 64 * APAD;
    float* Vs  = sm + 2 * 64 * APAD;

    int tid = threadIdx.x;
    int qt = gridDim.x - 1 - blockIdx.x;   // reversed: long blocks first
    int bh = blockIdx.y;
    int q0 = qt * 64;

    const float* qb = gq + (size_t)bh * Ss * Dd;
    const float* kb = gk + (size_t)bh * Ss * Dd;
    const float* vb = gv + (size_t)bh * Ss * Dd;

    int lrow = tid >> 2;
    int lpart = tid & 3;
    int rg = tid >> 4;      // 0..15
    int cg = tid & 15;      // 0..15

    #pragma unroll
    for (int i = 0; i < 4; i++) {
        float4 v = *(const float4*)&qb[(size_t)(q0 + lrow) * Dd + (lpart + i * 4) * 4];
        v.x *= QSCALE; v.y *= QSCALE; v.z *= QSCALE; v.w *= QSCALE;
        *(float4*)&Qs[lrow * APAD + (lpart + i * 4) * 4] = v;
    }

    float mi[4], li[4];
    float4 acc[4];
    #pragma unroll
    for (int i = 0; i < 4; i++) {
        mi[i] = -INFINITY; li[i] = 0.f;
        acc[i] = make_float4(0.f, 0.f, 0.f, 0.f);
    }

    for (int kt = 0; kt <= qt; kt++) {
        int k0 = kt * 64;
        __syncthreads();   // prev-iter KPs/Vs readers done; orders Qs writes (kt==0)
        #pragma unroll
        for (int i = 0; i < 4; i++) {
            *(float4*)&KPs[lrow * APAD + (lpart + i * 4) * 4] =
                *(const float4*)&kb[(size_t)(k0 + lrow) * Dd + (lpart + i * 4) * 4];
            *(float4*)&Vs[lrow * APAD + (lpart + i * 4) * 4] =
                *(const float4*)&vb[(size_t)(k0 + lrow) * Dd + (lpart + i * 4) * 4];
        }
        __syncthreads();

        float s[4][4];
        #pragma unroll
        for (int i = 0; i < 4; i++)
            #pragma unroll
            for (int j = 0; j < 4; j++) s[i][j] = 0.f;

        #pragma unroll 4
        for (int d4 = 0; d4 < 16; d4++) {
            float4 q4[4], k4[4];
            #pragma unroll
            for (int i = 0; i < 4; i++)
                q4[i] = *(const float4*)&Qs[(rg + 16 * i) * APAD + d4 * 4];
            #pragma unroll
            for (int j = 0; j < 4; j++)
                k4[j] = *(const float4*)&KPs[(cg + 16 * j) * APAD + d4 * 4];
            #pragma unroll
            for (int i = 0; i < 4; i++)
                #pragma unroll
                for (int j = 0; j < 4; j++)
                    s[i][j] = fmaf(q4[i].x, k4[j].x, fmaf(q4[i].y, k4[j].y,
                              fmaf(q4[i].z, k4[j].z, fmaf(q4[i].w, k4[j].w, s[i][j]))));
        }

        if (kt == qt) {   // diagonal tile: causal mask
            #pragma unroll
            for (int i = 0; i < 4; i++)
                #pragma unroll
                for (int j = 0; j < 4; j++)
                    if (cg + 16 * j > rg + 16 * i) s[i][j] = -1e30f;
        }

        #pragma unroll
        for (int i = 0; i < 4; i++) {
            float mt = fmaxf(fmaxf(s[i][0], s[i][1]), fmaxf(s[i][2], s[i][3]));
            mt = fmaxf(mt, __shfl_xor_sync(0xffffffffu, mt, 1));
            mt = fmaxf(mt, __shfl_xor_sync(0xffffffffu, mt, 2));
            mt = fmaxf(mt, __shfl_xor_sync(0xffffffffu, mt, 4));
            mt = fmaxf(mt, __shfl_xor_sync(0xffffffffu, mt, 8));
            float mnew = fmaxf(mi[i], mt);
            float corr = fast_exp2(mi[i] - mnew);
            float lt = 0.f;
            #pragma unroll
            for (int j = 0; j < 4; j++) { s[i][j] = fast_exp2(s[i][j] - mnew); lt += s[i][j]; }
            lt += __shfl_xor_sync(0xffffffffu, lt, 1);
            lt += __shfl_xor_sync(0xffffffffu, lt, 2);
            lt += __shfl_xor_sync(0xffffffffu, lt, 4);
            lt += __shfl_xor_sync(0xffffffffu, lt, 8);
            li[i] = li[i] * corr + lt;
            mi[i] = mnew;
            acc[i].x *= corr; acc[i].y *= corr; acc[i].z *= corr; acc[i].w *= corr;
        }

        __syncthreads();   // all reads of KPs-as-K complete
        #pragma unroll
        for (int i = 0; i < 4; i++)
            #pragma unroll
            for (int j = 0; j < 4; j++)
                KPs[(rg + 16 * i) * APAD + cg + 16 * j] = s[i][j];
        __syncthreads();

        #pragma unroll 8
        for (int kk = 0; kk < 64; kk++) {
            float4 v4 = *(const float4*)&Vs[kk * APAD + cg * 4];
            #pragma unroll
            for (int i = 0; i < 4; i++) {
                float p = KPs[(rg + 16 * i) * APAD + kk];
                acc[i].x = fmaf(p, v4.x, acc[i].x);
                acc[i].y = fmaf(p, v4.y, acc[i].y);
                acc[i].z = fmaf(p, v4.z, acc[i].z);
                acc[i].w = fmaf(p, v4.w, acc[i].w);
            }
        }
    }

    int b = bh >> 4, h = bh & 15;
    #pragma unroll
    for (int i = 0; i < 4; i++) {
        float inv = 1.f / li[i];
        acc[i].x *= inv; acc[i].y *= inv; acc[i].z *= inv; acc[i].w *= inv;
        float* dst = gao + ((size_t)(b * Ss + q0 + rg + 16 * i) * Ee + h * Dd + cg * 4);
        *(float4*)dst = acc[i];
    }
}

// ============================================================
// launch
// ============================================================
extern "C" void kernel_launch(void* const* d_in, const int* in_sizes, int n_in,
                              void* d_out, int out_size)
{
    const float* xq = (const float*)d_in[0];
    const float* xk = (const float*)d_in[1];
    const float* xv = (const float*)d_in[2];
    // d_in[3] = mask, ignored (causal computed analytically)
    const float* Wq = (const float*)d_in[4];
    const float* bq = (const float*)d_in[5];
    const float* Wk = (const float*)d_in[6];
    const float* bk = (const float*)d_in[7];
    const float* Wv = (const float*)d_in[8];
    const float* bv = (const float*)d_in[9];
    const float* Wo = (const float*)d_in[10];
    const float* bo = (const float*)d_in[11];
    float* out = (float*)d_out;

    void *pWT, *pq, *pk, *pv, *pao;
    cudaGetSymbolAddress(&pWT, g_WT);
    cudaGetSymbolAddress(&pq,  g_q);
    cudaGetSymbolAddress(&pk,  g_k);
    cudaGetSymbolAddress(&pv,  g_v);
    cudaGetSymbolAddress(&pao, g_ao);
    float* WT  = (float*)pWT;
    float* qd  = (float*)pq;
    float* kd  = (float*)pk;
    float* vd  = (float*)pv;
    float* aod = (float*)pao;

    cudaFuncSetAttribute(attn_kernel, cudaFuncAttributeMaxDynamicSharedMemorySize, ASMEM);
    cudaFuncSetAttribute(gemm_tf32_kernel, cudaFuncAttributeMaxDynamicSharedMemorySize, GSMEM);

    transpose4_kernel<<<dim3(Kdim / 32, Ndim / 32, 4), dim3(32, 8)>>>(Wq, Wk, Wv, Wo);

    // Fused QKV projections: 24 x 32 blocks (mat = bx>>3 selects A/B/bias/C)
    gemm_tf32_kernel<<<dim3(24, Mtot / BM), 256, GSMEM>>>(
        xq, xk, xv, WT, bq, bk, bv, qd, kd, vd, 1);

    attn_kernel<<<dim3(Ss / 64, Bb * Hh), 256, ASMEM>>>(qd, kd, vd, aod);

    // Output projection: mat 0 only
    gemm_tf32_kernel<<<dim3(8, Mtot / BM), 256, GSMEM>>>(
        aod, aod, aod, WT + 3 * Ee * Ee, bo, bo, bo, out, out, out, 0);
}

// round 11
// speedup vs baseline: 1.0857x; 1.0857x over previous
#include <cuda_runtime.h>
#include <math.h>
#include <stdint.h>

// Problem constants
#define Bb 2
#define Ss 2048
#define Ee 1024
#define Hh 16
#define Dd 64
#define Mtot (Bb*Ss)   // 4096
#define Kdim Ee        // 1024
#define Ndim Ee        // 1024

// -------- device scratch (no allocations allowed) --------
__device__ float g_WT[4][Ee*Ee];          // transposed weights
__device__ float g_q[Bb*Hh*Ss*Dd];        // (b,h,s,d)
__device__ float g_k[Bb*Hh*Ss*Dd];
__device__ float g_v[Bb*Hh*Ss*Dd];
__device__ float g_ao[Mtot*Ee];           // attention output (b,s,h*D+d)

// ============================================================
// Transpose all 4 weight matrices: WT[k][n] = W[n][k]
// ============================================================
__global__ void transpose4_kernel(const float* __restrict__ w0, const float* __restrict__ w1,
                                  const float* __restrict__ w2, const float* __restrict__ w3)
{
    __shared__ float t[32][33];
    const float* W = (blockIdx.z == 0) ? w0 : (blockIdx.z == 1) ? w1 : (blockIdx.z == 2) ? w2 : w3;
    float* WT = g_WT[blockIdx.z];

    int x = blockIdx.x * 32 + threadIdx.x;   // k
    int y = blockIdx.y * 32 + threadIdx.y;   // n
    #pragma unroll
    for (int i = 0; i < 32; i += 8)
        t[threadIdx.y + i][threadIdx.x] = W[(size_t)(y + i) * Kdim + x];
    __syncthreads();
    x = blockIdx.y * 32 + threadIdx.x;       // n
    y = blockIdx.x * 32 + threadIdx.y;       // k
    #pragma unroll
    for (int i = 0; i < 32; i += 8)
        WT[(size_t)(y + i) * Ndim + x] = t[threadIdx.x][threadIdx.y + i];
}

// ============================================================
// 3xTF32 tensor-core GEMM.  blockIdx.x = mat*8 + n_tile; per-mat
// A/B/bias/C selection (QKV fused in one launch; O uses mat 0).
// mode 0: row-major C.  mode 1: head-split write (b,h,s,d).
// 128x128 block, BK=16, 256 thr = 8 warps (2x4), warp tile 64x32.
// R10 ncu: regs=160 -> 1 CTA/SM, tensor 45.8% + L1 45.2% (neither
// saturated). __launch_bounds__(256,2) caps regs at 128 -> 2 CTA/SM
// so one CTA's LDS/sync phases overlap the other's HMMA bursts.
// ============================================================
#define BM 128
#define BN 128
#define BK 16
#define ASTR 20
#define BSTR 136
#define ABUF (BM*ASTR)
#define BBUF (BK*BSTR)
#define BUFSZ (2*ABUF + 2*BBUF)
#define GSMEM (2*BUFSZ*4)        // 75776 bytes

__device__ __forceinline__ unsigned f2tf32(float x) {
    unsigned u; asm("cvt.rna.tf32.f32 %0, %1;" : "=r"(u) : "f"(x)); return u;
}

__device__ __forceinline__ void split_store4(float* hi, float* lo, float4 v) {
    float hx = __uint_as_float(f2tf32(v.x));
    float hy = __uint_as_float(f2tf32(v.y));
    float hz = __uint_as_float(f2tf32(v.z));
    float hw = __uint_as_float(f2tf32(v.w));
    *(float4*)hi = make_float4(hx, hy, hz, hw);
    *(float4*)lo = make_float4(__uint_as_float(f2tf32(v.x - hx)),
                               __uint_as_float(f2tf32(v.y - hy)),
                               __uint_as_float(f2tf32(v.z - hz)),
                               __uint_as_float(f2tf32(v.w - hw)));
}

__device__ __forceinline__ void mma_tf32(float* c, const unsigned* a, const unsigned* b) {
    asm volatile("mma.sync.aligned.m16n8k8.row.col.f32.tf32.tf32.f32 "
        "{%0,%1,%2,%3}, {%4,%5,%6,%7}, {%8,%9}, {%0,%1,%2,%3};"
        : "+f"(c[0]), "+f"(c[1]), "+f"(c[2]), "+f"(c[3])
        : "r"(a[0]), "r"(a[1]), "r"(a[2]), "r"(a[3]), "r"(b[0]), "r"(b[1]));
}

__global__ __launch_bounds__(256, 2) void gemm_tf32_kernel(
    const float* __restrict__ A0, const float* __restrict__ A1,
    const float* __restrict__ A2, const float* __restrict__ WTbase,
    const float* __restrict__ bias0, const float* __restrict__ bias1,
    const float* __restrict__ bias2,
    float* __restrict__ C0, float* __restrict__ C1, float* __restrict__ C2,
    int mode)
{
    extern __shared__ float smw[];
    int tid = threadIdx.x;
    int wid = tid >> 5, lane = tid & 31;
    int g = lane >> 2, kq = lane & 3;

    int mat = blockIdx.x >> 3;
    const float* A    = (mat == 0) ? A0 : (mat == 1) ? A1 : A2;
    const float* Bmat = WTbase + (size_t)mat * Ee * Ee;
    const float* bias = (mat == 0) ? bias0 : (mat == 1) ? bias1 : bias2;
    float* C          = (mat == 0) ? C0 : (mat == 1) ? C1 : C2;

    int m0 = blockIdx.y * BM, n0 = (blockIdx.x & 7) * BN;
    int wm = (wid >> 2) * 64, wn = (wid & 3) * 32;

    int ar = tid >> 1;              // 0..127 (A row)
    int ak = (tid & 1) * 8;         // 0 or 8
    int br = tid >> 4;              // 0..15  (B row = k)
    int bn = (tid & 15) * 4;        // +0, +64

    const float* Ag = A + (size_t)(m0 + ar) * Kdim + ak;
    const float* Bg = Bmat + (size_t)br * Ndim + n0 + bn;

    float c[4][4][4];
    #pragma unroll
    for (int i = 0; i < 4; i++)
        #pragma unroll
        for (int j = 0; j < 4; j++)
            #pragma unroll
            for (int t = 0; t < 4; t++) c[i][j][t] = 0.f;

    float4 va0, va1, vb0, vb1;

    va0 = *(const float4*)Ag;
    va1 = *(const float4*)(Ag + 4);
    vb0 = *(const float4*)Bg;
    vb1 = *(const float4*)(Bg + 64);
    {
        float* Ah = smw;              float* Al = Ah + ABUF;
        float* Bh = smw + 2 * ABUF;   float* Bl = Bh + BBUF;
        split_store4(&Ah[ar*ASTR + ak],     &Al[ar*ASTR + ak],     va0);
        split_store4(&Ah[ar*ASTR + ak + 4], &Al[ar*ASTR + ak + 4], va1);
        split_store4(&Bh[br*BSTR + bn],      &Bl[br*BSTR + bn],      vb0);
        split_store4(&Bh[br*BSTR + bn + 64], &Bl[br*BSTR + bn + 64], vb1);
    }
    __syncthreads();

    int buf = 0;
    for (int k0 = 0; k0 < Kdim; k0 += BK) {
        bool nxt = (k0 + BK) < Kdim;
        if (nxt) {
            va0 = *(const float4*)(Ag + k0 + BK);
            va1 = *(const float4*)(Ag + k0 + BK + 4);
            vb0 = *(const float4*)(Bg + (size_t)(k0 + BK) * Ndim);
            vb1 = *(const float4*)(Bg + (size_t)(k0 + BK) * Ndim + 64);
        }

        const float* Ah = smw + buf * BUFSZ;
        const float* Al = Ah + ABUF;
        const float* Bh = Ah + 2 * ABUF;
        const float* Bl = Bh + BBUF;

        #pragma unroll
        for (int ks = 0; ks < 2; ks++) {
            int k8 = ks * 8;
            unsigned bhf[4][2], blf[4][2];
            #pragma unroll
            for (int tn = 0; tn < 4; tn++) {
                int colb = wn + 8 * tn + g;
                bhf[tn][0] = __float_as_uint(Bh[(k8 + kq) * BSTR + colb]);
                bhf[tn][1] = __float_as_uint(Bh[(k8 + kq + 4) * BSTR + colb]);
                blf[tn][0] = __float_as_uint(Bl[(k8 + kq) * BSTR + colb]);
                blf[tn][1] = __float_as_uint(Bl[(k8 + kq + 4) * BSTR + colb]);
            }
            #pragma unroll
            for (int tm = 0; tm < 4; tm++) {
                int r0 = wm + 16 * tm + g;
                unsigned ahf[4], alf[4];
                ahf[0] = __float_as_uint(Ah[(r0    ) * ASTR + k8 + kq]);
                ahf[1] = __float_as_uint(Ah[(r0 + 8) * ASTR + k8 + kq]);
                ahf[2] = __float_as_uint(Ah[(r0    ) * ASTR + k8 + kq + 4]);
                ahf[3] = __float_as_uint(Ah[(r0 + 8) * ASTR + k8 + kq + 4]);
                alf[0] = __float_as_uint(Al[(r0    ) * ASTR + k8 + kq]);
                alf[1] = __float_as_uint(Al[(r0 + 8) * ASTR + k8 + kq]);
                alf[2] = __float_as_uint(Al[(r0    ) * ASTR + k8 + kq + 4]);
                alf[3] = __float_as_uint(Al[(r0 + 8) * ASTR + k8 + kq + 4]);
                #pragma unroll
                for (int tn = 0; tn < 4; tn++) {
                    mma_tf32(c[tm][tn], ahf, bhf[tn]);   // hi*hi
                    mma_tf32(c[tm][tn], alf, bhf[tn]);   // lo*hi
                    mma_tf32(c[tm][tn], ahf, blf[tn]);   // hi*lo
                }
            }
        }

        if (nxt) {
            int nb = buf ^ 1;
            float* nAh = smw + nb * BUFSZ;  float* nAl = nAh + ABUF;
            float* nBh = nAh + 2 * ABUF;    float* nBl = nBh + BBUF;
            split_store4(&nAh[ar*ASTR + ak],     &nAl[ar*ASTR + ak],     va0);
            split_store4(&nAh[ar*ASTR + ak + 4], &nAl[ar*ASTR + ak + 4], va1);
            split_store4(&nBh[br*BSTR + bn],      &nBl[br*BSTR + bn],      vb0);
            split_store4(&nBh[br*BSTR + bn + 64], &nBl[br*BSTR + bn + 64], vb1);
            __syncthreads();
            buf = nb;
        }
    }

    #pragma unroll
    for (int tn = 0; tn < 4; tn++) {
        int col = n0 + wn + 8 * tn + 2 * kq;
        float b0 = bias[col], b1 = bias[col + 1];
        #pragma unroll
        for (int tm = 0; tm < 4; tm++) {
            int ma = m0 + wm + 16 * tm + g;
            int mb = ma + 8;
            float2 ra = make_float2(c[tm][tn][0] + b0, c[tm][tn][1] + b1);
            float2 rb = make_float2(c[tm][tn][2] + b0, c[tm][tn][3] + b1);
            if (mode == 0) {
                *(float2*)&C[(size_t)ma * Ndim + col] = ra;
                *(float2*)&C[(size_t)mb * Ndim + col] = rb;
            } else {
                int h = col >> 6, d = col & 63;
                int ba_ = ma >> 11, sa = ma & 2047;
                int bb_ = mb >> 11, sb = mb & 2047;
                *(float2*)&C[((size_t)(ba_ * Hh + h) * Ss + sa) * Dd + d] = ra;
                *(float2*)&C[((size_t)(bb_ * Hh + h) * Ss + sb) * Dd + d] = rb;
            }
        }
    }
}

// ============================================================
// Fast exp2 on the FMA pipe (MUFU rt=8/SMSP would bottleneck softmax).
// Domain after clamp: [-126, 0]; max rel err ~4e-5.
// ============================================================
__device__ __forceinline__ float fast_exp2(float x) {
    x = fmaxf(x, -126.f);
    float r = rintf(x);
    float f = x - r;                  // [-0.5, 0.5]
    float p = 0.00961812910f;
    p = fmaf(p, f, 0.05550410866f);
    p = fmaf(p, f, 0.24022650696f);
    p = fmaf(p, f, 0.69314718056f);
    p = fmaf(p, f, 1.0f);
    int e = (int)r;
    return p * __int_as_float((e + 127) << 23);
}

// ============================================================
// Flash attention, causal, base-2 softmax. 64x64 tiles, 256 threads.
// Thread microtile: rows rg+16i (i<4) x score cols cg+16j (j<4);
// output dims cg*4..cg*4+3.  (Unchanged this round — clean attribution
// of the GEMM occupancy change; attn is the round-12 target.)
// ============================================================
#define APAD 68
#define ASMEM (3 * 64 * APAD * 4)
#define QSCALE (0.125f * 1.44269504088896340736f)

__global__ __launch_bounds__(256) void attn_kernel(
    const float* __restrict__ gq, const float* __restrict__ gk,
    const float* __restrict__ gv, float* __restrict__ gao)
{
    extern __shared__ float sm[];
    float* Qs  = sm;
    float* KPs = sm + 64 * APAD;
    float* Vs  = sm + 2 * 64 * APAD;

    int tid = threadIdx.x;
    int qt = gridDim.x - 1 - blockIdx.x;   // reversed: long blocks first
    int bh = blockIdx.y;
    int q0 = qt * 64;

    const float* qb = gq + (size_t)bh * Ss * Dd;
    const float* kb = gk + (size_t)bh * Ss * Dd;
    const float* vb = gv + (size_t)bh * Ss * Dd;

    int lrow = tid >> 2;
    int lpart = tid & 3;
    int rg = tid >> 4;      // 0..15
    int cg = tid & 15;      // 0..15

    #pragma unroll
    for (int i = 0; i < 4; i++) {
        float4 v = *(const float4*)&qb[(size_t)(q0 + lrow) * Dd + (lpart + i * 4) * 4];
        v.x *= QSCALE; v.y *= QSCALE; v.z *= QSCALE; v.w *= QSCALE;
        *(float4*)&Qs[lrow * APAD + (lpart + i * 4) * 4] = v;
    }

    float mi[4], li[4];
    float4 acc[4];
    #pragma unroll
    for (int i = 0; i < 4; i++) {
        mi[i] = -INFINITY; li[i] = 0.f;
        acc[i] = make_float4(0.f, 0.f, 0.f, 0.f);
    }

    for (int kt = 0; kt <= qt; kt++) {
        int k0 = kt * 64;
        __syncthreads();   // prev-iter KPs/Vs readers done; orders Qs writes (kt==0)
        #pragma unroll
        for (int i = 0; i < 4; i++) {
            *(float4*)&KPs[lrow * APAD + (lpart + i * 4) * 4] =
                *(const float4*)&kb[(size_t)(k0 + lrow) * Dd + (lpart + i * 4) * 4];
            *(float4*)&Vs[lrow * APAD + (lpart + i * 4) * 4] =
                *(const float4*)&vb[(size_t)(k0 + lrow) * Dd + (lpart + i * 4) * 4];
        }
        __syncthreads();

        float s[4][4];
        #pragma unroll
        for (int i = 0; i < 4; i++)
            #pragma unroll
            for (int j = 0; j < 4; j++) s[i][j] = 0.f;

        #pragma unroll 4
        for (int d4 = 0; d4 < 16; d4++) {
            float4 q4[4], k4[4];
            #pragma unroll
            for (int i = 0; i < 4; i++)
                q4[i] = *(const float4*)&Qs[(rg + 16 * i) * APAD + d4 * 4];
            #pragma unroll
            for (int j = 0; j < 4; j++)
                k4[j] = *(const float4*)&KPs[(cg + 16 * j) * APAD + d4 * 4];
            #pragma unroll
            for (int i = 0; i < 4; i++)
                #pragma unroll
                for (int j = 0; j < 4; j++)
                    s[i][j] = fmaf(q4[i].x, k4[j].x, fmaf(q4[i].y, k4[j].y,
                              fmaf(q4[i].z, k4[j].z, fmaf(q4[i].w, k4[j].w, s[i][j]))));
        }

        if (kt == qt) {   // diagonal tile: causal mask
            #pragma unroll
            for (int i = 0; i < 4; i++)
                #pragma unroll
                for (int j = 0; j < 4; j++)
                    if (cg + 16 * j > rg + 16 * i) s[i][j] = -1e30f;
        }

        #pragma unroll
        for (int i = 0; i < 4; i++) {
            float mt = fmaxf(fmaxf(s[i][0], s[i][1]), fmaxf(s[i][2], s[i][3]));
            mt = fmaxf(mt, __shfl_xor_sync(0xffffffffu, mt, 1));
            mt = fmaxf(mt, __shfl_xor_sync(0xffffffffu, mt, 2));
            mt = fmaxf(mt, __shfl_xor_sync(0xffffffffu, mt, 4));
            mt = fmaxf(mt, __shfl_xor_sync(0xffffffffu, mt, 8));
            float mnew = fmaxf(mi[i], mt);
            float corr = fast_exp2(mi[i] - mnew);
            float lt = 0.f;
            #pragma unroll
            for (int j = 0; j < 4; j++) { s[i][j] = fast_exp2(s[i][j] - mnew); lt += s[i][j]; }
            lt += __shfl_xor_sync(0xffffffffu, lt, 1);
            lt += __shfl_xor_sync(0xffffffffu, lt, 2);
            lt += __shfl_xor_sync(0xffffffffu, lt, 4);
            lt += __shfl_xor_sync(0xffffffffu, lt, 8);
            li[i] = li[i] * corr + lt;
            mi[i] = mnew;
            acc[i].x *= corr; acc[i].y *= corr; acc[i].z *= corr; acc[i].w *= corr;
        }

        __syncthreads();   // all reads of KPs-as-K complete
        #pragma unroll
        for (int i = 0; i < 4; i++)
            #pragma unroll
            for (int j = 0; j < 4; j++)
                KPs[(rg + 16 * i) * APAD + cg + 16 * j] = s[i][j];
        __syncthreads();

        #pragma unroll 8
        for (int kk = 0; kk < 64; kk++) {
            float4 v4 = *(const float4*)&Vs[kk * APAD + cg * 4];
            #pragma unroll
            for (int i = 0; i < 4; i++) {
                float p = KPs[(rg + 16 * i) * APAD + kk];
                acc[i].x = fmaf(p, v4.x, acc[i].x);
                acc[i].y = fmaf(p, v4.y, acc[i].y);
                acc[i].z = fmaf(p, v4.z, acc[i].z);
                acc[i].w = fmaf(p, v4.w, acc[i].w);
            }
        }
    }

    int b = bh >> 4, h = bh & 15;
    #pragma unroll
    for (int i = 0; i < 4; i++) {
        float inv = 1.f / li[i];
        acc[i].x *= inv; acc[i].y *= inv; acc[i].z *= inv; acc[i].w *= inv;
        float* dst = gao + ((size_t)(b * Ss + q0 + rg + 16 * i) * Ee + h * Dd + cg * 4);
        *(float4*)dst = acc[i];
    }
}

// ============================================================
// launch
// ============================================================
extern "C" void kernel_launch(void* const* d_in, const int* in_sizes, int n_in,
                              void* d_out, int out_size)
{
    const float* xq = (const float*)d_in[0];
    const float* xk = (const float*)d_in[1];
    const float* xv = (const float*)d_in[2];
    // d_in[3] = mask, ignored (causal computed analytically)
    const float* Wq = (const float*)d_in[4];
    const float* bq = (const float*)d_in[5];
    const float* Wk = (const float*)d_in[6];
    const float* bk = (const float*)d_in[7];
    const float* Wv = (const float*)d_in[8];
    const float* bv = (const float*)d_in[9];
    const float* Wo = (const float*)d_in[10];
    const float* bo = (const float*)d_in[11];
    float* out = (float*)d_out;

    void *pWT, *pq, *pk, *pv, *pao;
    cudaGetSymbolAddress(&pWT, g_WT);
    cudaGetSymbolAddress(&pq,  g_q);
    cudaGetSymbolAddress(&pk,  g_k);
    cudaGetSymbolAddress(&pv,  g_v);
    cudaGetSymbolAddress(&pao, g_ao);
    float* WT  = (float*)pWT;
    float* qd  = (float*)pq;
    float* kd  = (float*)pk;
    float* vd  = (float*)pv;
    float* aod = (float*)pao;

    cudaFuncSetAttribute(attn_kernel, cudaFuncAttributeMaxDynamicSharedMemorySize, ASMEM);
    cudaFuncSetAttribute(gemm_tf32_kernel, cudaFuncAttributeMaxDynamicSharedMemorySize, GSMEM);

    transpose4_kernel<<<dim3(Kdim / 32, Ndim / 32, 4), dim3(32, 8)>>>(Wq, Wk, Wv, Wo);

    // Fused QKV projections: 24 x 32 blocks (mat = bx>>3 selects A/B/bias/C)
    gemm_tf32_kernel<<<dim3(24, Mtot / BM), 256, GSMEM>>>(
        xq, xk, xv, WT, bq, bk, bv, qd, kd, vd, 1);

    attn_kernel<<<dim3(Ss / 64, Bb * Hh), 256, ASMEM>>>(qd, kd, vd, aod);

    // Output projection: mat 0 only
    gemm_tf32_kernel<<<dim3(8, Mtot / BM), 256, GSMEM>>>(
        aod, aod, aod, WT + 3 * Ee * Ee, bo, bo, bo, out, out, out, 0);
}